// round 1
// baseline (speedup 1.0000x reference)
#include <cuda_runtime.h>
#include <math.h>

#define B 128
#define T 64
#define I 196
#define D 512
#define TEMP 0.07f

#define KC 16          // K tile
#define IC 128         // image-token chunk per pass (196 -> 2 chunks, masked)
#define TPAD 68        // padded smem row (64 text) : 68 = 4*17, 16B-aligned rows, conflict-staggered
#define IPAD 132       // padded smem row (128 img) : 132 = 4*33

// Scratch: sim matrix [B,B] (NOT divided by temperature yet)
__device__ float g_sim[B * B];

__global__ __launch_bounds__(128, 4)
void sim_kernel(const float* __restrict__ img, const float* __restrict__ txt) {
    const int b2 = blockIdx.x;   // image batch
    const int b1 = blockIdx.y;   // text batch
    const float* tptr = txt + (size_t)b1 * T * D;
    const float* iptr = img + (size_t)b2 * I * D;

    __shared__ float Ts[KC][TPAD];    // transposed: [k][text_row]
    __shared__ float Is[KC][IPAD];    // transposed: [k][img_row]
    __shared__ float red[T][17];      // max-reduction buffer (padded)
    __shared__ float rowres[T];

    const int tid = threadIdx.x;      // 128 threads
    const int ty = tid >> 4;          // 0..7  -> text rows ty*8..ty*8+7
    const int tx = tid & 15;          // 0..15 -> img cols  tx*8..tx*8+7

    float rowmax[8];
    #pragma unroll
    for (int j = 0; j < 8; j++) rowmax[j] = -1e30f;

    for (int chunk = 0; chunk < 2; chunk++) {
        const int ibase = chunk * IC;
        float acc[8][8];
        #pragma unroll
        for (int j = 0; j < 8; j++)
            #pragma unroll
            for (int l = 0; l < 8; l++) acc[j][l] = 0.0f;

        for (int kt = 0; kt < D / KC; kt++) {
            const int k0 = kt * KC;
            // ---- load text tile: 64 rows x 16 k = 256 float4, 2 per thread ----
            #pragma unroll
            for (int q = 0; q < 2; q++) {
                int f  = tid * 2 + q;        // 0..255
                int t  = f >> 2;             // 0..63
                int kq = f & 3;              // which float4 in the 16-wide k tile
                float4 v = *(const float4*)(tptr + (size_t)t * D + k0 + kq * 4);
                Ts[kq * 4 + 0][t] = v.x;
                Ts[kq * 4 + 1][t] = v.y;
                Ts[kq * 4 + 2][t] = v.z;
                Ts[kq * 4 + 3][t] = v.w;
            }
            // ---- load image tile: 128 rows x 16 k = 512 float4, 4 per thread ----
            #pragma unroll
            for (int q = 0; q < 4; q++) {
                int f  = tid * 4 + q;        // 0..511
                int r  = f >> 2;             // 0..127 (row within chunk)
                int kq = f & 3;
                int gi = ibase + r;
                float4 v = make_float4(0.f, 0.f, 0.f, 0.f);
                if (gi < I) v = *(const float4*)(iptr + (size_t)gi * D + k0 + kq * 4);
                Is[kq * 4 + 0][r] = v.x;
                Is[kq * 4 + 1][r] = v.y;
                Is[kq * 4 + 2][r] = v.z;
                Is[kq * 4 + 3][r] = v.w;
            }
            __syncthreads();

            #pragma unroll
            for (int k = 0; k < KC; k++) {
                float a[8], bb[8];
                *(float4*)&a[0]  = *(const float4*)&Ts[k][ty * 8];
                *(float4*)&a[4]  = *(const float4*)&Ts[k][ty * 8 + 4];
                *(float4*)&bb[0] = *(const float4*)&Is[k][tx * 8];
                *(float4*)&bb[4] = *(const float4*)&Is[k][tx * 8 + 4];
                #pragma unroll
                for (int j = 0; j < 8; j++)
                    #pragma unroll
                    for (int l = 0; l < 8; l++)
                        acc[j][l] = fmaf(a[j], bb[l], acc[j][l]);
            }
            __syncthreads();
        }

        // fold this chunk into the running per-row max (mask padded img cols)
        #pragma unroll
        for (int j = 0; j < 8; j++) {
            #pragma unroll
            for (int l = 0; l < 8; l++) {
                int gi = ibase + tx * 8 + l;
                if (gi < I) rowmax[j] = fmaxf(rowmax[j], acc[j][l]);
            }
        }
    }

    // cross-thread max over the 16 tx groups, then mean over 64 text rows
    #pragma unroll
    for (int j = 0; j < 8; j++) red[ty * 8 + j][tx] = rowmax[j];
    __syncthreads();

    if (tid < T) {
        float m = red[tid][0];
        #pragma unroll
        for (int x = 1; x < 16; x++) m = fmaxf(m, red[tid][x]);
        rowres[tid] = m;
    }
    __syncthreads();

    if (tid == 0) {
        float s = 0.0f;
        #pragma unroll 8
        for (int t = 0; t < T; t++) s += rowres[t];
        g_sim[b1 * B + b2] = s * (1.0f / (float)T);
    }
}

__global__ void loss_kernel(float* __restrict__ out) {
    __shared__ float acc[B];
    const int b = threadIdx.x;   // 0..127

    // row-wise LSE (i2t): logits[b, :]
    float m = -1e30f;
    for (int j = 0; j < B; j++) m = fmaxf(m, g_sim[b * B + j]);
    float s = 0.0f;
    for (int j = 0; j < B; j++) s += expf((g_sim[b * B + j] - m) * (1.0f / TEMP));
    float lse_row = m * (1.0f / TEMP) + logf(s);

    // col-wise LSE (t2i): logits[:, b]
    float mc = -1e30f;
    for (int j = 0; j < B; j++) mc = fmaxf(mc, g_sim[j * B + b]);
    float sc = 0.0f;
    for (int j = 0; j < B; j++) sc += expf((g_sim[j * B + b] - mc) * (1.0f / TEMP));
    float lse_col = mc * (1.0f / TEMP) + logf(sc);

    float diag = g_sim[b * B + b] * (1.0f / TEMP);
    acc[b] = (lse_row - diag) + (lse_col - diag);
    __syncthreads();

    for (int st = B / 2; st > 0; st >>= 1) {
        if (b < st) acc[b] += acc[b + st];
        __syncthreads();
    }
    if (b == 0) out[0] = acc[0] * 0.5f / (float)B;
}

extern "C" void kernel_launch(void* const* d_in, const int* in_sizes, int n_in,
                              void* d_out, int out_size) {
    // Identify inputs by element count (image: 128*196*512, text: 128*64*512)
    const float* img;
    const float* txt;
    if (in_sizes[0] == B * I * D) {
        img = (const float*)d_in[0];
        txt = (const float*)d_in[1];
    } else {
        img = (const float*)d_in[1];
        txt = (const float*)d_in[0];
    }

    dim3 grid(B, B);
    sim_kernel<<<grid, 128>>>(img, txt);
    loss_kernel<<<1, B>>>((float*)d_out);
}

// round 8
// speedup vs baseline: 2.5059x; 2.5059x over previous
#include <cuda_runtime.h>
#include <cuda_bf16.h>
#include <stdint.h>
#include <math.h>

#define BSZ  128
#define TTOK 64
#define ITOK 196
#define DIM  512
#define TEMP 0.07f

#define KTOT 1536                 // 3 * 512 (split-bf16: ah*bh + ah*bl + al*bh)
#define NPAD 208                  // image tokens padded to 16-multiple
#define CH   24                   // K chunks of 64 halves
#define CTA_M 128
#define STAGES 3
#define A_STAGE 16384             // 128 rows * 128 B
#define B_STAGE 26624             // 208 rows * 128 B
#define STAGE_B (A_STAGE + B_STAGE)
#define DSMEM (STAGES * STAGE_B)  // 129024

// Packed bf16 operands.
// A [8192][1536]: text rows, cols = [ah(512) | ah(512) | al(512)]
// B [128][208][1536]: image rows (zero-padded 196..207), cols = [bh | bl | bh]
__device__ __align__(128) __nv_bfloat16 g_A[(size_t)8192 * KTOT];
__device__ __align__(128) __nv_bfloat16 g_B[(size_t)BSZ * NPAD * KTOT];
__device__ float g_sim[BSZ * BSZ];

__device__ __forceinline__ uint32_t s2u(const void* p) {
    uint32_t a;
    asm("{ .reg .u64 t; cvta.to.shared.u64 t, %1; cvt.u32.u64 %0, t; }"
        : "=r"(a) : "l"(p));
    return a;
}

// ---------------- prep: fp32 -> split bf16, packed ----------------
__global__ void prep_txt(const float* __restrict__ txt) {
    int idx = blockIdx.x * 256 + threadIdx.x;   // r*512 + k
    int r = idx >> 9, k = idx & 511;
    float x = txt[idx];
    __nv_bfloat16 hi = __float2bfloat16(x);
    __nv_bfloat16 lo = __float2bfloat16(x - __bfloat162float(hi));
    size_t base = (size_t)r * KTOT;
    g_A[base + k]        = hi;
    g_A[base + 512 + k]  = hi;
    g_A[base + 1024 + k] = lo;
}

__global__ void prep_img(const float* __restrict__ img) {
    int idx = blockIdx.x * 256 + threadIdx.x;   // ((b2*208 + r)*512 + k)
    int k = idx & 511;
    int rr = idx >> 9;
    int r = rr % NPAD;
    int b2 = rr / NPAD;
    float x = (r < ITOK) ? img[((size_t)b2 * ITOK + r) * DIM + k] : 0.0f;
    __nv_bfloat16 hi = __float2bfloat16(x);
    __nv_bfloat16 lo = __float2bfloat16(x - __bfloat162float(hi));
    size_t base = (size_t)rr * KTOT;
    g_B[base + k]        = hi;
    g_B[base + 512 + k]  = lo;
    g_B[base + 1024 + k] = hi;
}

// ---------------- main GEMM + maxsim ----------------
__device__ __forceinline__ void load_chunk(uint32_t sb, int s, int c, int tid,
                                           const unsigned char* Ag,
                                           const unsigned char* Bg) {
    uint32_t sA = sb + s * STAGE_B;
    uint32_t sB = sA + A_STAGE;
    #pragma unroll
    for (int i = 0; i < 4; i++) {                       // A: 1024 x 16B
        int idx = tid + i * 256;
        int r = idx >> 3, t = idx & 7;
        uint32_t d = sA + r * 128 + ((t ^ (r & 7)) << 4);
        const unsigned char* g = Ag + (size_t)r * (KTOT * 2) + c * 128 + t * 16;
        asm volatile("cp.async.cg.shared.global [%0], [%1], 16;\n"
                     :: "r"(d), "l"(g));
    }
    #pragma unroll
    for (int i = 0; i < 7; i++) {                       // B: 1664 x 16B
        int idx = tid + i * 256;
        if (idx < 1664) {
            int r = idx >> 3, t = idx & 7;
            uint32_t d = sB + r * 128 + ((t ^ (r & 7)) << 4);
            const unsigned char* g = Bg + (size_t)r * (KTOT * 2) + c * 128 + t * 16;
            asm volatile("cp.async.cg.shared.global [%0], [%1], 16;\n"
                         :: "r"(d), "l"(g));
        }
    }
}

#define LDSM_X4(r0, r1, r2, r3, addr) \
    asm volatile("ldmatrix.sync.aligned.m8n8.x4.shared.b16 {%0,%1,%2,%3}, [%4];" \
                 : "=r"(r0), "=r"(r1), "=r"(r2), "=r"(r3) : "r"(addr))
#define LDSM_X2(r0, r1, addr) \
    asm volatile("ldmatrix.sync.aligned.m8n8.x2.shared.b16 {%0,%1}, [%2];" \
                 : "=r"(r0), "=r"(r1) : "r"(addr))
#define MMA_BF16(c, a, b0, b1) \
    asm volatile("mma.sync.aligned.m16n8k16.row.col.f32.bf16.bf16.f32 " \
                 "{%0,%1,%2,%3}, {%4,%5,%6,%7}, {%8,%9}, {%0,%1,%2,%3};" \
                 : "+f"((c)[0]), "+f"((c)[1]), "+f"((c)[2]), "+f"((c)[3]) \
                 : "r"((a)[0]), "r"((a)[1]), "r"((a)[2]), "r"((a)[3]), \
                   "r"(b0), "r"(b1))

__global__ void __launch_bounds__(256, 1) sim_kernel() {
    extern __shared__ __align__(128) unsigned char smem[];
    const uint32_t sb = s2u(smem);
    const int b2 = blockIdx.x;
    const int mt = blockIdx.y;          // text-row tile: rows mt*128..+127
    const int tid = threadIdx.x;
    const int lane = tid & 31;
    const int wid = tid >> 5;
    const int warp_m = (wid & 3) * 32;
    const int wn = wid >> 2;            // 0/1
    const int warp_n = wn * 104;

    __shared__ float maxbuf[128][2];
    __shared__ float rowbuf[128];

    const unsigned char* Ag =
        (const unsigned char*)g_A + (size_t)mt * CTA_M * (KTOT * 2);
    const unsigned char* Bg =
        (const unsigned char*)g_B + (size_t)b2 * NPAD * (KTOT * 2);

    // per-lane ldmatrix row/col selectors
    const int ra = warp_m + (lane & 15);       // A rows (+ mi*16)
    const int a_sel = lane >> 4;               // 0/1 -> k0 / k0+8
    const int rb = warp_n + (lane & 7);        // B rows (+ ni*8)
    const int b_sel = (lane >> 3) & 1;

    float acc[2][13][4];
    #pragma unroll
    for (int mi = 0; mi < 2; mi++)
        #pragma unroll
        for (int ni = 0; ni < 13; ni++)
            #pragma unroll
            for (int q = 0; q < 4; q++) acc[mi][ni][q] = 0.0f;

    // prologue: fill the pipeline
    #pragma unroll
    for (int s = 0; s < STAGES; s++) {
        load_chunk(sb, s, s, tid, Ag, Bg);
        asm volatile("cp.async.commit_group;\n");
    }

    for (int c = 0; c < CH; c++) {
        asm volatile("cp.async.wait_group 2;\n");
        __syncthreads();
        uint32_t sA = sb + (c % STAGES) * STAGE_B;
        uint32_t sB = sA + A_STAGE;

        #pragma unroll
        for (int kk = 0; kk < 4; kk++) {                 // 4 k16 steps per chunk
            uint32_t a0[4], a1[4];
            {
                int t = kk * 2 + a_sel;
                int r0 = ra;
                uint32_t ad0 = sA + r0 * 128 + ((t ^ (r0 & 7)) << 4);
                LDSM_X4(a0[0], a0[1], a0[2], a0[3], ad0);
                int r1 = ra + 16;
                uint32_t ad1 = sA + r1 * 128 + ((t ^ (r1 & 7)) << 4);
                LDSM_X4(a1[0], a1[1], a1[2], a1[3], ad1);
            }
            #pragma unroll
            for (int ni = 0; ni < 13; ni++) {
                int r = rb + ni * 8;
                int t = kk * 2 + b_sel;
                uint32_t bd = sB + r * 128 + ((t ^ (r & 7)) << 4);
                uint32_t b0, b1;
                LDSM_X2(b0, b1, bd);
                MMA_BF16(acc[0][ni], a0, b0, b1);
                MMA_BF16(acc[1][ni], a1, b0, b1);
            }
        }
        __syncthreads();
        if (c + STAGES < CH) load_chunk(sb, c % STAGES, c + STAGES, tid, Ag, Bg);
        asm volatile("cp.async.commit_group;\n");
    }

    // -------- epilogue: masked max over n, reduce, mean over t --------
    float rmax[4];                       // [mi*2 + half], half: row T/4 vs +8
    #pragma unroll
    for (int j = 0; j < 4; j++) rmax[j] = -1e30f;

    #pragma unroll
    for (int mi = 0; mi < 2; mi++)
        #pragma unroll
        for (int ni = 0; ni < 13; ni++)
            #pragma unroll
            for (int q = 0; q < 4; q++) {
                int n = warp_n + ni * 8 + (lane & 3) * 2 + (q & 1);
                if (n < ITOK) {
                    int j = mi * 2 + (q >> 1);
                    rmax[j] = fmaxf(rmax[j], acc[mi][ni][q]);
                }
            }

    #pragma unroll
    for (int j = 0; j < 4; j++) {
        rmax[j] = fmaxf(rmax[j], __shfl_xor_sync(0xffffffffu, rmax[j], 1));
        rmax[j] = fmaxf(rmax[j], __shfl_xor_sync(0xffffffffu, rmax[j], 2));
    }
    if ((lane & 3) == 0) {
        #pragma unroll
        for (int j = 0; j < 4; j++) {
            int row = warp_m + (j >> 1) * 16 + (lane >> 2) + (j & 1) * 8;
            maxbuf[row][wn] = rmax[j];
        }
    }
    __syncthreads();

    if (tid < 128) rowbuf[tid] = fmaxf(maxbuf[tid][0], maxbuf[tid][1]);
    __syncthreads();

    if (tid < 2) {
        float s = 0.0f;
        #pragma unroll 8
        for (int j = 0; j < 64; j++) s += rowbuf[tid * 64 + j];
        g_sim[(2 * mt + tid) * BSZ + b2] = s * (1.0f / 64.0f);
    }
}

// ---------------- loss ----------------
__global__ void loss_kernel(float* __restrict__ out) {
    __shared__ float acc[BSZ];
    const int b = threadIdx.x;

    float m = -1e30f;
    for (int j = 0; j < BSZ; j++) m = fmaxf(m, g_sim[b * BSZ + j]);
    float s = 0.0f;
    for (int j = 0; j < BSZ; j++) s += expf((g_sim[b * BSZ + j] - m) * (1.0f / TEMP));
    float lse_row = m * (1.0f / TEMP) + logf(s);

    float mc = -1e30f;
    for (int j = 0; j < BSZ; j++) mc = fmaxf(mc, g_sim[j * BSZ + b]);
    float sc = 0.0f;
    for (int j = 0; j < BSZ; j++) sc += expf((g_sim[j * BSZ + b] - mc) * (1.0f / TEMP));
    float lse_col = mc * (1.0f / TEMP) + logf(sc);

    float diag = g_sim[b * BSZ + b] * (1.0f / TEMP);
    acc[b] = (lse_row - diag) + (lse_col - diag);
    __syncthreads();
    for (int st = BSZ / 2; st > 0; st >>= 1) {
        if (b < st) acc[b] += acc[b + st];
        __syncthreads();
    }
    if (b == 0) out[0] = acc[0] * 0.5f / (float)BSZ;
}

// ---------------- launch ----------------
extern "C" void kernel_launch(void* const* d_in, const int* in_sizes, int n_in,
                              void* d_out, int out_size) {
    const float* img;
    const float* txt;
    if (in_sizes[0] == BSZ * ITOK * DIM) {
        img = (const float*)d_in[0];
        txt = (const float*)d_in[1];
    } else {
        img = (const float*)d_in[1];
        txt = (const float*)d_in[0];
    }

    prep_txt<<<(8192 * DIM) / 256, 256>>>(txt);
    prep_img<<<(BSZ * NPAD * DIM) / 256, 256>>>(img);

    cudaFuncSetAttribute(sim_kernel, cudaFuncAttributeMaxDynamicSharedMemorySize,
                         DSMEM);
    dim3 grid(BSZ, 64);
    sim_kernel<<<grid, 256, DSMEM>>>();

    loss_kernel<<<1, BSZ>>>((float*)d_out);
}